// round 2
// baseline (speedup 1.0000x reference)
#include <cuda_runtime.h>
#include <cstdint>
#include <cstdio>

#define BB 4
#define TT 12
#define NNODE 2000
#define NEDGE 32000
#define NDIM 16
#define EDIM 8
#define NH 4
#define DD 16
#define GG 64
#define GHH 64
#define BT 48   // BB*TT

// ---------------- scratch (device globals; no allocation allowed) ----------------
static __device__ float    g_h   [(size_t)BT*NNODE*GG];     // node projections
static __device__ float    g_sd  [(size_t)BT*NNODE*NH];
static __device__ float    g_ss  [(size_t)BT*NNODE*NH];
static __device__ float    g_score[(size_t)BT*NEDGE*NH];    // score -> exp -> alpha
static __device__ unsigned g_smax[(size_t)BT*NNODE*NH];
static __device__ float    g_ssum[(size_t)BT*NNODE*NH];
static __device__ float    g_agg [(size_t)BT*NNODE*GG];
static __device__ float    g_gin [(size_t)BB*NNODE*TT*GG];  // LN output, row=(b*N+n)*T+t
static __device__ float    g_gi  [(size_t)BB*NNODE*TT*3*GHH]; // precomputed input gates
static __device__ float    g_Md[NDIM*NH], g_Ms[NDIM*NH], g_Me[EDIM*NH];
static __device__ int      g_src[NEDGE], g_dst[NEDGE];

// ordered-uint encoding for float atomicMax (handles negatives)
static __device__ __forceinline__ unsigned fenc(float f) {
    unsigned u = __float_as_uint(f);
    return (u & 0x80000000u) ? ~u : (u | 0x80000000u);
}
static __device__ __forceinline__ float fdec(unsigned v) {
    return (v & 0x80000000u) ? __uint_as_float(v ^ 0x80000000u) : __uint_as_float(~v);
}

// ---------------- kernel 1: zero scratch + copy edge_index (int32!) ----------------
__global__ void k_init(const int* __restrict__ ei) {
    size_t idx = (size_t)blockIdx.x * blockDim.x + threadIdx.x;
    if (idx < (size_t)BT*NNODE*GG) g_agg[idx] = 0.f;
    if (idx < (size_t)BT*NNODE*NH) { g_ssum[idx] = 0.f; g_smax[idx] = 0u; }
    if (idx < NEDGE) { g_src[idx] = ei[idx]; g_dst[idx] = ei[NEDGE + idx]; }
}

// ---------------- kernel 2: fold att vectors into projection matrices ----------------
// Md[c][h] = sum_d W_node[c, h*D+d] * a_dst[h][d], etc.
__global__ void k_prep(const float* __restrict__ Wn, const float* __restrict__ We,
                       const float* __restrict__ att) {
    int tid = threadIdx.x;
    if (tid < NDIM*NH) {
        int c = tid >> 2, h = tid & 3;
        float s0 = 0.f, s1 = 0.f;
        #pragma unroll
        for (int d = 0; d < DD; d++) {
            float w = Wn[c*GG + h*DD + d];
            s0 += w * att[h*(3*DD) + d];
            s1 += w * att[h*(3*DD) + DD + d];
        }
        g_Md[c*NH + h] = s0;
        g_Ms[c*NH + h] = s1;
    } else if (tid < NDIM*NH + EDIM*NH) {
        int k = tid - NDIM*NH;
        int c = k >> 2, h = k & 3;
        float s = 0.f;
        #pragma unroll
        for (int d = 0; d < DD; d++)
            s += We[c*GG + h*DD + d] * att[h*(3*DD) + 2*DD + d];
        g_Me[c*NH + h] = s;
    }
}

// ---------------- kernel 3: node projection + per-node score terms ----------------
__global__ void k_node(const float* __restrict__ xf, const float* __restrict__ Wn) {
    __shared__ float xs[NDIM];
    int gn = blockIdx.x;            // [0, BT*NNODE)
    int j  = threadIdx.x;           // 64
    if (j < NDIM) xs[j] = xf[(size_t)gn*NDIM + j];
    __syncthreads();
    float acc = 0.f;
    #pragma unroll
    for (int c = 0; c < NDIM; c++) acc += xs[c] * __ldg(&Wn[c*GG + j]);
    g_h[(size_t)gn*GG + j] = acc;
    if (j < 2*NH) {
        const float* M = (j < NH) ? g_Md : g_Ms;
        int h = j & 3;
        float s = 0.f;
        #pragma unroll
        for (int c = 0; c < NDIM; c++) s += xs[c] * M[c*NH + h];
        if (j < NH) g_sd[(size_t)gn*NH + h] = s;
        else        g_ss[(size_t)gn*NH + h] = s;
    }
}

// ---------------- kernel 4: edge scores + segment max ----------------
__global__ void k_score(const float* __restrict__ efeat) {
    int id = blockIdx.x * blockDim.x + threadIdx.x;   // [0, BT*NEDGE)
    if (id >= BT*NEDGE) return;
    int g = id / NEDGE, e = id - g*NEDGE;
    const float* ef = efeat + (size_t)id * EDIM;
    float4 e0 = *reinterpret_cast<const float4*>(ef);
    float4 e1 = *reinterpret_cast<const float4*>(ef + 4);
    float efv[8] = {e0.x, e0.y, e0.z, e0.w, e1.x, e1.y, e1.z, e1.w};
    int dst = g_dst[e], src = g_src[e];
    size_t dbase = ((size_t)g*NNODE + dst) * NH;
    size_t sbase = ((size_t)g*NNODE + src) * NH;
    float4 sd4 = *reinterpret_cast<const float4*>(&g_sd[dbase]);
    float4 ss4 = *reinterpret_cast<const float4*>(&g_ss[sbase]);
    float sdv[4] = {sd4.x, sd4.y, sd4.z, sd4.w};
    float ssv[4] = {ss4.x, ss4.y, ss4.z, ss4.w};
    float outv[4];
    #pragma unroll
    for (int h = 0; h < NH; h++) {
        float se = 0.f;
        #pragma unroll
        for (int c = 0; c < EDIM; c++) se += efv[c] * g_Me[c*NH + h];
        float sc = sdv[h] + ssv[h] + se;
        sc = (sc > 0.f) ? sc : 0.2f * sc;      // leaky_relu(0.2)
        outv[h] = sc;
        atomicMax(&g_smax[dbase + h], fenc(sc));
    }
    *reinterpret_cast<float4*>(&g_score[(size_t)id*NH]) =
        make_float4(outv[0], outv[1], outv[2], outv[3]);
}

// ---------------- kernel 5: exp(score - max) + segment sum ----------------
__global__ void k_expsum() {
    int id = blockIdx.x * blockDim.x + threadIdx.x;
    if (id >= BT*NEDGE) return;
    int g = id / NEDGE, e = id - g*NEDGE;
    int dst = g_dst[e];
    size_t dbase = ((size_t)g*NNODE + dst) * NH;
    float4 sc = *reinterpret_cast<const float4*>(&g_score[(size_t)id*NH]);
    uint4  mx = *reinterpret_cast<const uint4*>(&g_smax[dbase]);
    float es0 = expf(sc.x - fdec(mx.x));
    float es1 = expf(sc.y - fdec(mx.y));
    float es2 = expf(sc.z - fdec(mx.z));
    float es3 = expf(sc.w - fdec(mx.w));
    *reinterpret_cast<float4*>(&g_score[(size_t)id*NH]) = make_float4(es0, es1, es2, es3);
    atomicAdd(&g_ssum[dbase + 0], es0);
    atomicAdd(&g_ssum[dbase + 1], es1);
    atomicAdd(&g_ssum[dbase + 2], es2);
    atomicAdd(&g_ssum[dbase + 3], es3);
}

// ---------------- kernel 6: alpha + message aggregation (one warp per edge) ----------------
__global__ void k_agg(const float* __restrict__ efeat, const float* __restrict__ We) {
    int wid = (blockIdx.x * blockDim.x + threadIdx.x) >> 5;   // edge-graph id
    if (wid >= BT*NEDGE) return;
    int lane = threadIdx.x & 31;
    int g = wid / NEDGE, e = wid - g*NEDGE;
    int dst = g_dst[e], src = g_src[e];
    float al = 0.f;
    if (lane < NH) {
        float es = g_score[(size_t)wid*NH + lane];
        float ssum = g_ssum[((size_t)g*NNODE + dst)*NH + lane];
        al = es / (ssum + 1e-16f);
        g_score[(size_t)wid*NH + lane] = al;   // keep alpha for attn output
    }
    const float* ef = efeat + (size_t)wid * EDIM;
    float efv[8];
    #pragma unroll
    for (int c = 0; c < EDIM; c++) efv[c] = __ldg(ef + c);   // broadcast
    const float* hs = g_h + ((size_t)g*NNODE + src) * GG;
    float* ag = g_agg + ((size_t)g*NNODE + dst) * GG;
    #pragma unroll
    for (int rep = 0; rep < 2; rep++) {
        int j = lane + rep*32;
        float ev = 0.f;
        #pragma unroll
        for (int c = 0; c < EDIM; c++) ev += efv[c] * __ldg(&We[c*GG + j]);
        float m = hs[j] + ev;
        float a = __shfl_sync(0xFFFFFFFFu, al, j >> 4);
        atomicAdd(&ag[j], a * m);
    }
}

// ---------------- kernel 7: attention output (mean over batch) ----------------
__global__ void k_attn(float* __restrict__ out3) {
    int idx = blockIdx.x * blockDim.x + threadIdx.x;   // [0, TT*NEDGE*NH)
    if (idx >= TT*NEDGE*NH) return;
    int h = idx & 3;
    int rest = idx >> 2;
    int e = rest % NEDGE;
    int t = rest / NEDGE;
    float s = 0.f;
    #pragma unroll
    for (int b = 0; b < BB; b++)
        s += g_score[(((size_t)(b*TT + t))*NEDGE + e)*NH + h];
    out3[idx] = 0.25f * s;
}

// ---------------- kernel 8: ELU + LayerNorm -> GRU input layout ----------------
__global__ void k_ln(const float* __restrict__ gamma, const float* __restrict__ beta) {
    int gn = blockIdx.x;                 // g*NNODE + n
    int j  = threadIdx.x;                // 64
    int g = gn / NNODE, n = gn - g*NNODE;
    float v = g_agg[(size_t)gn*GG + j];
    v = (v > 0.f) ? v : (expf(v) - 1.f);  // elu
    __shared__ float tmp[2];
    float s = v;
    #pragma unroll
    for (int off = 16; off; off >>= 1) s += __shfl_xor_sync(0xFFFFFFFFu, s, off);
    if ((j & 31) == 0) tmp[j >> 5] = s;
    __syncthreads();
    float mu = (tmp[0] + tmp[1]) * (1.f / GG);
    __syncthreads();
    float d = v - mu;
    float q = d * d;
    #pragma unroll
    for (int off = 16; off; off >>= 1) q += __shfl_xor_sync(0xFFFFFFFFu, q, off);
    if ((j & 31) == 0) tmp[j >> 5] = q;
    __syncthreads();
    float var = (tmp[0] + tmp[1]) * (1.f / GG);
    float o = d * rsqrtf(var + 1e-5f) * gamma[j] + beta[j];
    int b = g / TT, t = g - b*TT;
    g_gin[(((size_t)b*NNODE + n)*TT + t)*GG + j] = o;
}

// ---------------- kernel 9: gi GEMM  gi[row] = gin[row] @ W_ih^T + b_ih ----------------
// rows = B*N*T = 96000, tile 64 rows/block, 256 threads, dyn smem 64KB
__global__ void k_gi(const float* __restrict__ Wih, const float* __restrict__ bih) {
    extern __shared__ float sm[];
    float* Wt = sm;                 // [64][192]  (transposed W_ih)
    float* X  = sm + 64*192;        // [64][64]
    int tid = threadIdx.x;
    for (int i = tid; i < 192*64; i += 256) {
        int o = i / 64, k = i - o*64;
        Wt[k*192 + o] = Wih[i];
    }
    size_t row0 = (size_t)blockIdx.x * 64;
    for (int i = tid; i < 64*64; i += 256) X[i] = g_gin[row0*GG + i];
    __syncthreads();
    int j  = tid & 63;
    int ty = tid >> 6;               // 0..3  (16 rows each)
    float acc[16][3];
    #pragma unroll
    for (int r = 0; r < 16; r++) { acc[r][0] = 0.f; acc[r][1] = 0.f; acc[r][2] = 0.f; }
    for (int k = 0; k < 64; k++) {
        float w0 = Wt[k*192 + j];
        float w1 = Wt[k*192 + 64 + j];
        float w2 = Wt[k*192 + 128 + j];
        #pragma unroll
        for (int r = 0; r < 16; r++) {
            float xv = X[(ty*16 + r)*64 + k];
            acc[r][0] += xv * w0;
            acc[r][1] += xv * w1;
            acc[r][2] += xv * w2;
        }
    }
    float b0 = bih[j], b1 = bih[j + 64], b2 = bih[j + 128];
    #pragma unroll
    for (int r = 0; r < 16; r++) {
        size_t row = row0 + ty*16 + r;
        size_t base = row * 192;
        g_gi[base + j]        = acc[r][0] + b0;
        g_gi[base + 64 + j]   = acc[r][1] + b1;
        g_gi[base + 128 + j]  = acc[r][2] + b2;
    }
}

// ---------------- kernel 10: fused GRU over T + h_i + pred outputs ----------------
// block = 256 threads = 4 GRU rows x 64, dyn smem ~51KB
__global__ void k_gru(const float* __restrict__ Whh, const float* __restrict__ bhh_g,
                      const float* __restrict__ Wout, const float* __restrict__ bout,
                      float* __restrict__ out) {
    extern __shared__ float sm[];
    float* Wt  = sm;                  // [64][192]
    float* hsh = sm + 64*192;         // [4][64]
    float* bhh = hsh + 4*64;          // [192]
    float* pp  = bhh + 192;           // [8]
    int tid = threadIdx.x;
    for (int i = tid; i < 192*64; i += 256) {
        int o = i / 64, k = i - o*64;
        Wt[k*192 + o] = Whh[i];
    }
    for (int i = tid; i < 192; i += 256) bhh[i] = bhh_g[i];
    int r = tid >> 6, j = tid & 63;
    hsh[r*64 + j] = 0.f;
    __syncthreads();
    float b_r = bhh[j], b_z = bhh[j + 64], b_n = bhh[j + 128];
    int row = blockIdx.x * 4 + r;                   // [0, B*N)
    const float* gi_base = g_gi + (size_t)row * TT * 192;
    float h = 0.f;
    for (int t = 0; t < TT; t++) {
        float ar = 0.f, az = 0.f, an = 0.f;
        #pragma unroll
        for (int k = 0; k < 64; k++) {
            float hk = hsh[r*64 + k];
            ar += hk * Wt[k*192 + j];
            az += hk * Wt[k*192 + 64 + j];
            an += hk * Wt[k*192 + 128 + j];
        }
        const float* gi = gi_base + t * 192;
        float rg = 1.f / (1.f + expf(-(gi[j]       + ar + b_r)));
        float zg = 1.f / (1.f + expf(-(gi[j + 64]  + az + b_z)));
        float ng = tanhf(gi[j + 128] + rg * (an + b_n));
        h = (1.f - zg) * ng + zg * h;
        __syncthreads();
        hsh[r*64 + j] = h;
        __syncthreads();
    }
    // h_i output (offset 8000)
    out[8000 + (size_t)row*GHH + j] = h;
    // pred = h . W_out + b_out
    float p = h * __ldg(&Wout[j]);
    #pragma unroll
    for (int off = 16; off; off >>= 1) p += __shfl_down_sync(0xFFFFFFFFu, p, off);
    if ((tid & 31) == 0) pp[tid >> 5] = p;
    __syncthreads();
    if (j == 0) out[row] = pp[r*2] + pp[r*2 + 1] + bout[0];
}

// ---------------- launch ----------------
extern "C" void kernel_launch(void* const* d_in, const int* in_sizes, int n_in,
                              void* d_out, int out_size) {
    const float* node_features = (const float*)d_in[0];
    const float* edge_features = (const float*)d_in[1];
    const float* W_node  = (const float*)d_in[2];
    const float* W_edge  = (const float*)d_in[3];
    const float* att     = (const float*)d_in[4];
    const float* ln_gamma= (const float*)d_in[5];
    const float* ln_beta = (const float*)d_in[6];
    const float* W_ih    = (const float*)d_in[7];
    const float* W_hh    = (const float*)d_in[8];
    const float* b_ih    = (const float*)d_in[9];
    const float* b_hh    = (const float*)d_in[10];
    const float* W_out   = (const float*)d_in[11];
    const float* b_out   = (const float*)d_in[12];
    const int*   edge_index = (const int*)d_in[13];   // JAX default x64=off -> int32
    float* out = (float*)d_out;

    cudaFuncSetAttribute(k_gi,  cudaFuncAttributeMaxDynamicSharedMemorySize, (64*192 + 64*64) * 4);
    cudaFuncSetAttribute(k_gru, cudaFuncAttributeMaxDynamicSharedMemorySize, (64*192 + 4*64 + 192 + 8) * 4);

    {   // init: zero agg/ssum/smax + edge index copy
        size_t n = (size_t)BT*NNODE*GG;
        k_init<<<(unsigned)((n + 255) / 256), 256>>>(edge_index);
    }
    k_prep<<<1, 128>>>(W_node, W_edge, att);
    k_node<<<BT*NNODE, 64>>>(node_features, W_node);
    k_score<<<(BT*NEDGE)/256, 256>>>(edge_features);
    k_expsum<<<(BT*NEDGE)/256, 256>>>();
    k_agg<<<(BT*NEDGE*32)/256, 256>>>(edge_features, W_edge);
    k_attn<<<(TT*NEDGE*NH)/256, 256>>>(out + 8000 + (size_t)BB*NNODE*GHH);
    k_ln<<<BT*NNODE, 64>>>(ln_gamma, ln_beta);
    k_gi<<<(BB*NNODE*TT)/64, 256, (64*192 + 64*64)*4>>>(W_ih, b_ih);
    k_gru<<<(BB*NNODE)/4, 256, (64*192 + 4*64 + 192 + 8)*4>>>(W_hh, b_hh, W_out, b_out, out);
}

// round 3
// speedup vs baseline: 1.2816x; 1.2816x over previous
#include <cuda_runtime.h>
#include <cstdint>
#include <cstdio>

#define BB 4
#define TT 12
#define NNODE 2000
#define NEDGE 32000
#define NDIM 16
#define EDIM 8
#define NH 4
#define DD 16
#define GG 64
#define GHH 64
#define BT 48   // BB*TT
#define MAXSORT 96

// ---------------- scratch (device globals) ----------------
static __device__ float    g_h   [(size_t)BT*NNODE*GG];     // node projections
static __device__ float    g_sd  [(size_t)BT*NNODE*NH];
static __device__ float    g_ss  [(size_t)BT*NNODE*NH];
static __device__ float    g_score[(size_t)BT*NEDGE*NH];    // score -> es (exp)
static __device__ float    g_rcp [(size_t)BT*NNODE*NH];     // 1/(sum es + eps)
static __device__ float    g_gin [(size_t)BB*NNODE*TT*GG];  // LN output, row=(b*N+n)*T+t
static __device__ float    g_gi  [(size_t)BB*NNODE*TT*3*GHH];
static __device__ float    g_Md[NDIM*NH], g_Ms[NDIM*NH], g_Me[EDIM*NH];
static __device__ int      g_src[NEDGE], g_dst[NEDGE];
static __device__ int      g_deg[NNODE], g_off[NNODE+1], g_cur[NNODE], g_csr[NEDGE];

// ---------------- CSR build ----------------
__global__ void k_zero() {
    int i = blockIdx.x * blockDim.x + threadIdx.x;
    if (i < NNODE) g_deg[i] = 0;
}

__global__ void k_count(const int* __restrict__ ei) {
    int e = blockIdx.x * blockDim.x + threadIdx.x;
    if (e < NEDGE) {
        int s = ei[e], d = ei[NEDGE + e];
        g_src[e] = s; g_dst[e] = d;
        atomicAdd(&g_deg[d], 1);
    }
}

__global__ void k_scan() {   // single block, 1024 threads, N<=2048
    __shared__ int a[2048], b[2048];
    int tid = threadIdx.x;
    for (int i = tid; i < 2048; i += 1024) a[i] = (i < NNODE) ? g_deg[i] : 0;
    __syncthreads();
    int* cur = a; int* nxt = b;
    for (int d = 1; d < 2048; d <<= 1) {
        for (int i = tid; i < 2048; i += 1024)
            nxt[i] = (i >= d) ? cur[i] + cur[i - d] : cur[i];
        __syncthreads();
        int* t = cur; cur = nxt; nxt = t;
    }
    for (int i = tid; i < NNODE; i += 1024) {
        int excl = (i == 0) ? 0 : cur[i - 1];
        g_off[i] = excl; g_cur[i] = excl;
    }
    if (tid == 0) g_off[NNODE] = cur[NNODE - 1];
}

__global__ void k_fill() {
    int e = blockIdx.x * blockDim.x + threadIdx.x;
    if (e < NEDGE) {
        int pos = atomicAdd(&g_cur[g_dst[e]], 1);
        g_csr[pos] = e;
    }
}

__global__ void k_sort() {   // deterministic order: sort each node's edge list
    int node = blockIdx.x * blockDim.x + threadIdx.x;
    if (node >= NNODE) return;
    int off = g_off[node];
    int deg = g_off[node + 1] - off;
    int m = deg < MAXSORT ? deg : MAXSORT;
    int buf[MAXSORT];
    for (int i = 0; i < m; i++) buf[i] = g_csr[off + i];
    for (int i = 1; i < m; i++) {
        int v = buf[i], k = i - 1;
        while (k >= 0 && buf[k] > v) { buf[k + 1] = buf[k]; k--; }
        buf[k + 1] = v;
    }
    for (int i = 0; i < m; i++) g_csr[off + i] = buf[i];
}

// ---------------- fold att vectors into tiny matrices ----------------
__global__ void k_prep(const float* __restrict__ Wn, const float* __restrict__ We,
                       const float* __restrict__ att) {
    int tid = threadIdx.x;
    if (tid < NDIM*NH) {
        int c = tid >> 2, h = tid & 3;
        float s0 = 0.f, s1 = 0.f;
        #pragma unroll
        for (int d = 0; d < DD; d++) {
            float w = Wn[c*GG + h*DD + d];
            s0 += w * att[h*(3*DD) + d];
            s1 += w * att[h*(3*DD) + DD + d];
        }
        g_Md[c*NH + h] = s0;
        g_Ms[c*NH + h] = s1;
    } else if (tid < NDIM*NH + EDIM*NH) {
        int k = tid - NDIM*NH;
        int c = k >> 2, h = k & 3;
        float s = 0.f;
        #pragma unroll
        for (int d = 0; d < DD; d++)
            s += We[c*GG + h*DD + d] * att[h*(3*DD) + 2*DD + d];
        g_Me[c*NH + h] = s;
    }
}

// ---------------- node projection + score terms (4 nodes/block) ----------------
__global__ void k_node(const float* __restrict__ xf, const float* __restrict__ Wn) {
    __shared__ float xs[4][NDIM];
    int sub = threadIdx.x >> 6;
    int j   = threadIdx.x & 63;
    int gn  = blockIdx.x * 4 + sub;     // [0, BT*NNODE)
    if (j < NDIM) xs[sub][j] = xf[(size_t)gn*NDIM + j];
    __syncthreads();
    float acc = 0.f;
    #pragma unroll
    for (int c = 0; c < NDIM; c++) acc += xs[sub][c] * __ldg(&Wn[c*GG + j]);
    g_h[(size_t)gn*GG + j] = acc;
    if (j < 2*NH) {
        const float* M = (j < NH) ? g_Md : g_Ms;
        int h = j & 3;
        float s = 0.f;
        #pragma unroll
        for (int c = 0; c < NDIM; c++) s += xs[sub][c] * M[c*NH + h];
        if (j < NH) g_sd[(size_t)gn*NH + h] = s;
        else        g_ss[(size_t)gn*NH + h] = s;
    }
}

// ---------------- fused GAT gather: score/max/exp/sum/alpha/agg/ELU/LN ----------------
// one warp per (graph, node); block = 8 warps; grid = (N/8, BT)
__global__ void k_gather(const float* __restrict__ efeat, const float* __restrict__ We,
                         const float* __restrict__ gamma, const float* __restrict__ beta) {
    int g    = blockIdx.y;
    int warp = threadIdx.x >> 5;
    int lane = threadIdx.x & 31;
    int node = blockIdx.x * 8 + warp;
    size_t gE = (size_t)g * NEDGE;
    size_t nb = (size_t)g * NNODE + node;

    // per-lane weights: lane owns components c0=lane, c1=lane+32
    float we0[EDIM], we1[EDIM];
    #pragma unroll
    for (int c8 = 0; c8 < EDIM; c8++) {
        we0[c8] = __ldg(&We[c8*GG + lane]);
        we1[c8] = __ldg(&We[c8*GG + lane + 32]);
    }
    float4 me4[EDIM];
    #pragma unroll
    for (int c8 = 0; c8 < EDIM; c8++)
        me4[c8] = *reinterpret_cast<const float4*>(&g_Me[c8*NH]);

    int off = g_off[node];
    int deg = g_off[node + 1] - off;
    float4 sd4 = *reinterpret_cast<const float4*>(&g_sd[nb*NH]);

    // pass A: scores + max
    float mx0 = -1e30f, mx1 = -1e30f, mx2 = -1e30f, mx3 = -1e30f;
    for (int i = lane; i < deg; i += 32) {
        int e = g_csr[off + i];
        int src = g_src[e];
        const float* ef = &efeat[(gE + e)*EDIM];
        float4 ea = *reinterpret_cast<const float4*>(ef);
        float4 eb = *reinterpret_cast<const float4*>(ef + 4);
        float efv[8] = {ea.x, ea.y, ea.z, ea.w, eb.x, eb.y, eb.z, eb.w};
        float4 ss4 = *reinterpret_cast<const float4*>(&g_ss[((size_t)g*NNODE + src)*NH]);
        float s0 = sd4.x + ss4.x, s1 = sd4.y + ss4.y, s2 = sd4.z + ss4.z, s3 = sd4.w + ss4.w;
        #pragma unroll
        for (int c8 = 0; c8 < EDIM; c8++) {
            s0 = fmaf(efv[c8], me4[c8].x, s0);
            s1 = fmaf(efv[c8], me4[c8].y, s1);
            s2 = fmaf(efv[c8], me4[c8].z, s2);
            s3 = fmaf(efv[c8], me4[c8].w, s3);
        }
        s0 = (s0 > 0.f) ? s0 : 0.2f*s0;  s1 = (s1 > 0.f) ? s1 : 0.2f*s1;
        s2 = (s2 > 0.f) ? s2 : 0.2f*s2;  s3 = (s3 > 0.f) ? s3 : 0.2f*s3;
        *reinterpret_cast<float4*>(&g_score[(gE + e)*NH]) = make_float4(s0, s1, s2, s3);
        mx0 = fmaxf(mx0, s0); mx1 = fmaxf(mx1, s1);
        mx2 = fmaxf(mx2, s2); mx3 = fmaxf(mx3, s3);
    }
    #pragma unroll
    for (int o = 16; o; o >>= 1) {
        mx0 = fmaxf(mx0, __shfl_xor_sync(0xFFFFFFFFu, mx0, o));
        mx1 = fmaxf(mx1, __shfl_xor_sync(0xFFFFFFFFu, mx1, o));
        mx2 = fmaxf(mx2, __shfl_xor_sync(0xFFFFFFFFu, mx2, o));
        mx3 = fmaxf(mx3, __shfl_xor_sync(0xFFFFFFFFu, mx3, o));
    }
    // pass B: exp + sum
    float sm0 = 0.f, sm1 = 0.f, sm2 = 0.f, sm3 = 0.f;
    for (int i = lane; i < deg; i += 32) {
        int e = g_csr[off + i];
        float4 sc = *reinterpret_cast<const float4*>(&g_score[(gE + e)*NH]);
        float e0 = __expf(sc.x - mx0), e1 = __expf(sc.y - mx1);
        float e2 = __expf(sc.z - mx2), e3 = __expf(sc.w - mx3);
        *reinterpret_cast<float4*>(&g_score[(gE + e)*NH]) = make_float4(e0, e1, e2, e3);
        sm0 += e0; sm1 += e1; sm2 += e2; sm3 += e3;
    }
    #pragma unroll
    for (int o = 16; o; o >>= 1) {
        sm0 += __shfl_xor_sync(0xFFFFFFFFu, sm0, o);
        sm1 += __shfl_xor_sync(0xFFFFFFFFu, sm1, o);
        sm2 += __shfl_xor_sync(0xFFFFFFFFu, sm2, o);
        sm3 += __shfl_xor_sync(0xFFFFFFFFu, sm3, o);
    }
    float rcp0 = 1.f/(sm0 + 1e-16f), rcp1 = 1.f/(sm1 + 1e-16f);
    float rcp2 = 1.f/(sm2 + 1e-16f), rcp3 = 1.f/(sm3 + 1e-16f);
    if (lane < 4)
        g_rcp[nb*NH + lane] = (lane == 0) ? rcp0 : (lane == 1) ? rcp1 : (lane == 2) ? rcp2 : rcp3;
    __syncwarp();   // make es visible cross-lane

    // pass C: aggregate messages (sequential over sorted edges -> deterministic)
    float myr0 = (lane < 16) ? rcp0 : rcp1;
    float myr1 = (lane < 16) ? rcp2 : rcp3;
    int h0 = lane >> 4;
    float acc0 = 0.f, acc1 = 0.f;
    for (int ei = 0; ei < deg; ei++) {
        int e = g_csr[off + ei];
        int src = g_src[e];
        const float* ef = &efeat[(gE + e)*EDIM];
        float v = (lane < 8) ? __ldg(ef + lane) : 0.f;
        const float* esp = &g_score[(gE + e)*NH];
        float al0 = esp[h0]     * myr0;
        float al1 = esp[2 + h0] * myr1;
        float ep0 = 0.f, ep1 = 0.f;
        #pragma unroll
        for (int c8 = 0; c8 < EDIM; c8++) {
            float ev = __shfl_sync(0xFFFFFFFFu, v, c8);
            ep0 = fmaf(ev, we0[c8], ep0);
            ep1 = fmaf(ev, we1[c8], ep1);
        }
        const float* hp = &g_h[((size_t)g*NNODE + src)*GG];
        acc0 = fmaf(al0, __ldg(hp + lane)      + ep0, acc0);
        acc1 = fmaf(al1, __ldg(hp + lane + 32) + ep1, acc1);
    }
    // ELU
    float a0 = (acc0 > 0.f) ? acc0 : (__expf(acc0) - 1.f);
    float a1 = (acc1 > 0.f) ? acc1 : (__expf(acc1) - 1.f);
    // LayerNorm over 64
    float s = a0 + a1;
    #pragma unroll
    for (int o = 16; o; o >>= 1) s += __shfl_xor_sync(0xFFFFFFFFu, s, o);
    float mu = s * (1.f/GG);
    float d0 = a0 - mu, d1 = a1 - mu;
    float q = d0*d0 + d1*d1;
    #pragma unroll
    for (int o = 16; o; o >>= 1) q += __shfl_xor_sync(0xFFFFFFFFu, q, o);
    float inv = rsqrtf(q * (1.f/GG) + 1e-5f);
    float o0 = d0*inv*__ldg(&gamma[lane])      + __ldg(&beta[lane]);
    float o1 = d1*inv*__ldg(&gamma[lane + 32]) + __ldg(&beta[lane + 32]);
    int b = g / TT, t = g - b*TT;
    size_t gb = (((size_t)b*NNODE + node)*TT + t)*GG;
    g_gin[gb + lane]      = o0;
    g_gin[gb + lane + 32] = o1;
}

// ---------------- attention output: mean over batch of es*rcp ----------------
__global__ void k_attn(float* __restrict__ out3) {
    int idx = blockIdx.x * blockDim.x + threadIdx.x;   // [0, TT*NEDGE*NH)
    if (idx >= TT*NEDGE*NH) return;
    int h = idx & 3;
    int rest = idx >> 2;
    int e = rest % NEDGE;
    int t = rest / NEDGE;
    int dst = g_dst[e];
    float s = 0.f;
    #pragma unroll
    for (int b = 0; b < BB; b++) {
        size_t gg = (size_t)(b*TT + t);
        float es = g_score[(gg*NEDGE + e)*NH + h];
        float rc = g_rcp  [(gg*NNODE + dst)*NH + h];
        s += es * rc;
    }
    out3[idx] = 0.25f * s;
}

// ---------------- gi GEMM: gi[row] = gin[row] @ W_ih^T + b_ih ----------------
__global__ void k_gi(const float* __restrict__ Wih, const float* __restrict__ bih) {
    extern __shared__ float sm[];
    float* Wt = sm;                 // [64][192]
    float* X  = sm + 64*192;        // [64][64]
    int tid = threadIdx.x;
    for (int i = tid; i < 192*64; i += 256) {
        int o = i / 64, k = i - o*64;
        Wt[k*192 + o] = Wih[i];
    }
    size_t row0 = (size_t)blockIdx.x * 64;
    for (int i = tid; i < 64*64; i += 256) X[i] = g_gin[row0*GG + i];
    __syncthreads();
    int j  = tid & 63;
    int ty = tid >> 6;
    float acc[16][3];
    #pragma unroll
    for (int r = 0; r < 16; r++) { acc[r][0] = 0.f; acc[r][1] = 0.f; acc[r][2] = 0.f; }
    for (int k = 0; k < 64; k++) {
        float w0 = Wt[k*192 + j];
        float w1 = Wt[k*192 + 64 + j];
        float w2 = Wt[k*192 + 128 + j];
        #pragma unroll
        for (int r = 0; r < 16; r++) {
            float xv = X[(ty*16 + r)*64 + k];
            acc[r][0] += xv * w0;
            acc[r][1] += xv * w1;
            acc[r][2] += xv * w2;
        }
    }
    float b0 = bih[j], b1 = bih[j + 64], b2 = bih[j + 128];
    #pragma unroll
    for (int r = 0; r < 16; r++) {
        size_t base = (row0 + ty*16 + r) * 192;
        g_gi[base + j]       = acc[r][0] + b0;
        g_gi[base + 64 + j]  = acc[r][1] + b1;
        g_gi[base + 128 + j] = acc[r][2] + b2;
    }
}

// ---------------- fused GRU: 32 nodes/block, 8 nodes/thread ----------------
// block 256 = 4 groups x 64 j; grid = 8000/32 = 250
__global__ void k_gru(const float* __restrict__ Whh, const float* __restrict__ bhh_g,
                      const float* __restrict__ Wout, const float* __restrict__ bout,
                      float* __restrict__ out) {
    extern __shared__ float sm[];
    float* Wt = sm;                       // [64][192]
    float* h0s = Wt + 64*192;             // [64][36] buf 0
    float* h1s = h0s + 64*36;             // [64][36] buf 1
    float* bs  = h1s + 64*36;             // [192]
    float* pp  = bs + 192;                // [32][2]
    int tid = threadIdx.x;
    for (int i = tid; i < 192*64; i += 256) {
        int o = i / 64, k = i - o*64;
        Wt[k*192 + o] = Whh[i];
    }
    for (int i = tid; i < 192; i += 256) bs[i] = bhh_g[i];
    __syncthreads();

    int j  = tid & 63;
    int ng = tid >> 6;                    // 0..3, owns nodes ng*8..ng*8+7
    int node0 = blockIdx.x * 32;
    float b_r = bs[j], b_z = bs[j + 64], b_n = bs[j + 128];

    const float* gp[8];
    #pragma unroll
    for (int i = 0; i < 8; i++)
        gp[i] = g_gi + (size_t)(node0 + ng*8 + i) * (TT*192);

    float h[8];
    // t = 0 : h_prev = 0 -> gh = b_hh
    #pragma unroll
    for (int i = 0; i < 8; i++) {
        float gr = __ldg(gp[i] + j), gz = __ldg(gp[i] + 64 + j), gn = __ldg(gp[i] + 128 + j);
        float r = 1.f/(1.f + __expf(-(gr + b_r)));
        float z = 1.f/(1.f + __expf(-(gz + b_z)));
        float n = tanhf(gn + r*b_n);
        h[i] = (1.f - z)*n;
    }
    {
        float* hb = h0s;
        #pragma unroll
        for (int i = 0; i < 8; i++) hb[j*36 + ng*8 + i] = h[i];
    }
    __syncthreads();

    for (int t = 1; t < TT; t++) {
        float* hin  = ((t - 1) & 1) ? h1s : h0s;
        float* hout = (t & 1) ? h1s : h0s;
        float ar[8], az[8], an[8];
        #pragma unroll
        for (int i = 0; i < 8; i++) { ar[i] = 0.f; az[i] = 0.f; an[i] = 0.f; }
        #pragma unroll 2
        for (int k = 0; k < 64; k++) {
            float w0 = Wt[k*192 + j];
            float w1 = Wt[k*192 + 64 + j];
            float w2 = Wt[k*192 + 128 + j];
            float4 ha = *reinterpret_cast<float4*>(&hin[k*36 + ng*8]);
            float4 hb = *reinterpret_cast<float4*>(&hin[k*36 + ng*8 + 4]);
            float hv[8] = {ha.x, ha.y, ha.z, ha.w, hb.x, hb.y, hb.z, hb.w};
            #pragma unroll
            for (int i = 0; i < 8; i++) {
                ar[i] = fmaf(hv[i], w0, ar[i]);
                az[i] = fmaf(hv[i], w1, az[i]);
                an[i] = fmaf(hv[i], w2, an[i]);
            }
        }
        const float* gbt = (const float*)(size_t)(t*192);
        #pragma unroll
        for (int i = 0; i < 8; i++) {
            float gr = __ldg(gp[i] + t*192 + j);
            float gz = __ldg(gp[i] + t*192 + 64 + j);
            float gn = __ldg(gp[i] + t*192 + 128 + j);
            float r = 1.f/(1.f + __expf(-(gr + ar[i] + b_r)));
            float z = 1.f/(1.f + __expf(-(gz + az[i] + b_z)));
            float n = tanhf(gn + r*(an[i] + b_n));
            h[i] = (1.f - z)*n + z*h[i];
        }
        #pragma unroll
        for (int i = 0; i < 8; i++) hout[j*36 + ng*8 + i] = h[i];
        __syncthreads();
        (void)gbt;
    }

    // outputs
    #pragma unroll
    for (int i = 0; i < 8; i++)
        out[8000 + (size_t)(node0 + ng*8 + i)*GHH + j] = h[i];
    float wj = __ldg(&Wout[j]);
    int half = (j >> 5);
    #pragma unroll
    for (int i = 0; i < 8; i++) {
        float p = h[i] * wj;
        #pragma unroll
        for (int o = 16; o; o >>= 1) p += __shfl_xor_sync(0xFFFFFFFFu, p, o);
        if ((j & 31) == 0) pp[(ng*8 + i)*2 + half] = p;
    }
    __syncthreads();
    if (tid < 32)
        out[node0 + tid] = pp[tid*2] + pp[tid*2 + 1] + __ldg(&bout[0]);
}

// ---------------- launch ----------------
extern "C" void kernel_launch(void* const* d_in, const int* in_sizes, int n_in,
                              void* d_out, int out_size) {
    const float* node_features = (const float*)d_in[0];
    const float* edge_features = (const float*)d_in[1];
    const float* W_node  = (const float*)d_in[2];
    const float* W_edge  = (const float*)d_in[3];
    const float* att     = (const float*)d_in[4];
    const float* ln_gamma= (const float*)d_in[5];
    const float* ln_beta = (const float*)d_in[6];
    const float* W_ih    = (const float*)d_in[7];
    const float* W_hh    = (const float*)d_in[8];
    const float* b_ih    = (const float*)d_in[9];
    const float* b_hh    = (const float*)d_in[10];
    const float* W_out   = (const float*)d_in[11];
    const float* b_out   = (const float*)d_in[12];
    const int*   edge_index = (const int*)d_in[13];   // int32 (JAX x64 off)
    float* out = (float*)d_out;

    static int smem_set = 0;
    int gi_smem  = (64*192 + 64*64) * 4;
    int gru_smem = (64*192 + 2*64*36 + 192 + 64) * 4;
    if (!smem_set) {
        cudaFuncSetAttribute(k_gi,  cudaFuncAttributeMaxDynamicSharedMemorySize, gi_smem);
        cudaFuncSetAttribute(k_gru, cudaFuncAttributeMaxDynamicSharedMemorySize, gru_smem);
        smem_set = 1;
    }

    // CSR build (edge list shared by all 48 graphs)
    k_zero <<<(NNODE + 255)/256, 256>>>();
    k_count<<<(NEDGE + 255)/256, 256>>>(edge_index);
    k_scan <<<1, 1024>>>();
    k_fill <<<(NEDGE + 255)/256, 256>>>();
    k_sort <<<(NNODE + 255)/256, 256>>>();

    k_prep<<<1, 128>>>(W_node, W_edge, att);
    k_node<<<BT*NNODE/4, 256>>>(node_features, W_node);

    dim3 ggrid(NNODE/8, BT);
    k_gather<<<ggrid, 256>>>(edge_features, W_edge, ln_gamma, ln_beta);

    k_attn<<<(TT*NEDGE*NH)/256, 256>>>(out + 8000 + (size_t)BB*NNODE*GHH);

    k_gi <<<(BB*NNODE*TT)/64, 256, gi_smem>>>(W_ih, b_ih);
    k_gru<<<(BB*NNODE)/32, 256, gru_smem>>>(W_hh, b_hh, W_out, b_out, out);
}